// round 9
// baseline (speedup 1.0000x reference)
#include <cuda_runtime.h>
#include <cstdint>

#define HID   16
#define BATCH 2048
#define SEQT  2048
#define FUT   32
#define NOUT  (FUT + 1)
#define WPB   16           // 16 warps/CTA, 128 CTAs -> 1 CTA/SM, 4 warps/SMSP uniform

typedef unsigned long long ull;

// ---------- packed f32x2 helpers (sm_103a) ----------
__device__ __forceinline__ ull pack2(float lo, float hi) {
    ull r;
    asm("mov.b64 %0, {%1, %2};" : "=l"(r) : "f"(lo), "f"(hi));
    return r;
}
__device__ __forceinline__ void unpack2(ull v, float& lo, float& hi) {
    asm("mov.b64 {%0, %1}, %2;" : "=f"(lo), "=f"(hi) : "l"(v));
}
__device__ __forceinline__ ull fma2(ull a, ull b, ull c) {
    ull d;
    asm("fma.rn.f32x2 %0, %1, %2, %3;" : "=l"(d) : "l"(a), "l"(b), "l"(c));
    return d;
}
__device__ __forceinline__ float hadd2(ull v) {
    float lo, hi; unpack2(v, lo, hi); return lo + hi;
}

// ---------- fast activations ----------
__device__ __forceinline__ float tanh_ap(float x) {
    float y;
    asm("tanh.approx.f32 %0, %1;" : "=f"(y) : "f"(x));
    return y;
}
__device__ __forceinline__ float sigm(float x) {
    return fmaf(0.5f, tanh_ap(0.5f * x), 0.5f);
}

// ONE warp = ONE batch element (max latency hiding; fma demand/SMSP is invariant
// in elements-per-warp, so spreading over 2x warps is free throughput-wise).
// lane = half*16 + j owns gate rows:  rowA = lane  (i_j for half0 / f_j for half1)
//                                     rowB = lane+32 (g_j / o_j)
// Gate exchange between halves: 2x shfl_xor(16); both halves compute c,h
// redundantly with identical fp order. h broadcast via smem STS.32 + 4x LDS.128
// (float4 == two packed f32x2 operands). Whh@h for t+1 pre-accumulated at t.
__global__ void __launch_bounds__(32 * WPB, 1)
lstm_net_kernel(const float* __restrict__ x,
                const float* __restrict__ Wih1, const float* __restrict__ Whh1,
                const float* __restrict__ bih1, const float* __restrict__ bhh1,
                const float* __restrict__ Wih2, const float* __restrict__ Whh2,
                const float* __restrict__ bih2, const float* __restrict__ bhh2,
                const float* __restrict__ fc1w, const float* __restrict__ fc1b,
                const float* __restrict__ fc2w, const float* __restrict__ fc2b,
                float* __restrict__ out)
{
    // Whh2 rowB (g/o rows) weights: [q][lane] = 2 k-pairs for k=4q..4q+3
    __shared__ ulonglong2 s_w2hB[4][32];
    // hidden-state broadcast: [warp][16 floats]
    __shared__ float4 s_h1[WPB][4];
    __shared__ float4 s_h2[WPB][4];
    // FC head
    __shared__ float s_fc1w[(HID / 2) * HID];
    __shared__ float s_fc1b[HID / 2];
    __shared__ float s_fc2w[HID / 2];
    __shared__ float s_fc2b;

    const int tid = threadIdx.x;
    if (tid < 128) {
        const int q = tid >> 5, l = tid & 31;      // rowB(lane l) == l + 32
        s_w2hB[q][l] = make_ulonglong2(
            pack2(Whh2[(l + 32) * HID + 4 * q],     Whh2[(l + 32) * HID + 4 * q + 1]),
            pack2(Whh2[(l + 32) * HID + 4 * q + 2], Whh2[(l + 32) * HID + 4 * q + 3]));
    }
    if (tid < (HID / 2) * HID) s_fc1w[tid] = fc1w[tid];
    if (tid < HID / 2) { s_fc1b[tid] = fc1b[tid]; s_fc2w[tid] = fc2w[tid]; }
    if (tid == 0) s_fc2b = fc2b[0];
    __syncthreads();

    const int lane = tid & 31;
    const int w    = tid >> 5;                  // warp in block (0..15)
    const int half = lane >> 4;                 // 0: (i,g) rows  1: (f,o) rows
    const int j    = lane & 15;                 // hidden unit
    const int b    = blockIdx.x * WPB + w;      // batch element

    const int rowA = lane;                      // j + 16*half
    const int rowB = lane + 32;

    // input weights + packed fused-bias constants
    const float wxA = Wih1[rowA], wxB = Wih1[rowB];
    const ull pbA1 = pack2(bih1[rowA] + bhh1[rowA], 0.f);
    const ull pbB1 = pack2(bih1[rowB] + bhh1[rowB], 0.f);
    const ull pbA2 = pack2(bih2[rowA] + bhh2[rowA], 0.f);
    const ull pbB2 = pack2(bih2[rowB] + bhh2[rowB], 0.f);

    // register-resident weights (k-pair packed): 5 arrays x 8 ull = 80 regs
    ull w1A[8], w1B[8], w2iA[8], w2iB[8], w2hA[8];
#pragma unroll
    for (int m = 0; m < 8; ++m) {
        w1A[m]  = pack2(Whh1[rowA * HID + 2 * m], Whh1[rowA * HID + 2 * m + 1]);
        w1B[m]  = pack2(Whh1[rowB * HID + 2 * m], Whh1[rowB * HID + 2 * m + 1]);
        w2iA[m] = pack2(Wih2[rowA * HID + 2 * m], Wih2[rowA * HID + 2 * m + 1]);
        w2iB[m] = pack2(Wih2[rowB * HID + 2 * m], Wih2[rowB * HID + 2 * m + 1]);
        w2hA[m] = pack2(Whh2[rowA * HID + 2 * m], Whh2[rowA * HID + 2 * m + 1]);
    }

    // carried state. p1* = b1 + Whh1@h1_prev ; p2* = Whh2@h2_prev
    float c1 = 0.f, c2 = 0.f, o_head = 0.f;
    ull p1A = pbA1, p1B = pbB1;
    ull p2A = pack2(0.f, 0.f), p2B = p2A;

    float* s_h1w = (float*)&s_h1[w];
    float* s_h2w = (float*)&s_h2[w];
    const ulonglong2* h1rd = (const ulonglong2*)&s_h1[w];
    const ulonglong2* h2rd = (const ulonglong2*)&s_h2[w];

    const float* xrow = x + (size_t)b * SEQT;
    float* orow = out + (size_t)b * NOUT;
    float xt = xrow[0];

#pragma unroll 1
    for (int t = 0; t < SEQT + FUT; ++t) {
        const float inp = (t < SEQT) ? xt : o_head;
        xt = xrow[(t + 1) & (SEQT - 1)];

        // ======== layer 1 gates ========
        const float uA = fmaf(wxA, inp, hadd2(p1A));
        const float uB = fmaf(wxB, inp, hadd2(p1B));
        const float vA = sigm(uA);                       // sigma(i) or sigma(f)
        float tb = tanh_ap(half ? 0.5f * uB : uB);
        const float vB = half ? fmaf(0.5f, tb, 0.5f) : tb;  // tanh(g) or sigma(o)
        const float xA = __shfl_xor_sync(0xffffffffu, vA, 16);
        const float xB = __shfl_xor_sync(0xffffffffu, vB, 16);
        const float iv = half ? xA : vA, fv = half ? vA : xA;
        const float gv = half ? xB : vB, ov = half ? vB : xB;
        c1 = fmaf(fv, c1, iv * gv);
        const float h1 = ov * tanh_ap(c1);

        // ==== broadcast h1; feeds Wih2 (now) + Whh1 (next step, in place) ====
        if (lane < 16) s_h1w[j] = h1;
        __syncwarp();

        ull a2A = pbA2, a2B = pbB2;
        p1A = pbA1; p1B = pbB1;
#pragma unroll
        for (int q = 0; q < 4; ++q) {
            const ulonglong2 hq = h1rd[q];               // k = 4q..4q+3
            a2A = fma2(w2iA[2 * q], hq.x, a2A);
            a2B = fma2(w2iB[2 * q], hq.x, a2B);
            p1A = fma2(w1A[2 * q], hq.x, p1A);
            p1B = fma2(w1B[2 * q], hq.x, p1B);
            a2A = fma2(w2iA[2 * q + 1], hq.y, a2A);
            a2B = fma2(w2iB[2 * q + 1], hq.y, a2B);
            p1A = fma2(w1A[2 * q + 1], hq.y, p1A);
            p1B = fma2(w1B[2 * q + 1], hq.y, p1B);
        }

        // ======== layer 2 gates ========
        const float u2A = hadd2(a2A) + hadd2(p2A);
        const float u2B = hadd2(a2B) + hadd2(p2B);
        const float wA = sigm(u2A);
        tb = tanh_ap(half ? 0.5f * u2B : u2B);
        const float wB = half ? fmaf(0.5f, tb, 0.5f) : tb;
        const float yA = __shfl_xor_sync(0xffffffffu, wA, 16);
        const float yB = __shfl_xor_sync(0xffffffffu, wB, 16);
        const float iv2 = half ? yA : wA, fv2 = half ? wA : yA;
        const float gv2 = half ? yB : wB, ov2 = half ? wB : yB;
        c2 = fmaf(fv2, c2, iv2 * gv2);
        const float h2 = ov2 * tanh_ap(c2);

        // ==== broadcast h2; pre-accumulate Whh2 @ h2 for next step ====
        if (lane < 16) s_h2w[j] = h2;
        __syncwarp();

        p2A = pack2(0.f, 0.f); p2B = p2A;
#pragma unroll
        for (int q = 0; q < 4; ++q) {
            const ulonglong2 hq = h2rd[q];
            const ulonglong2 wBq = s_w2hB[q][lane];
            p2A = fma2(w2hA[2 * q], hq.x, p2A);
            p2B = fma2(wBq.x, hq.x, p2B);
            p2A = fma2(w2hA[2 * q + 1], hq.y, p2A);
            p2B = fma2(wBq.y, hq.y, p2B);
        }

        // ======== head (last teacher step + future steps only) ========
        if (t >= SEQT - 1) {
            const int jj = lane & 7;
            float acc = s_fc1b[jj];
#pragma unroll
            for (int k = 0; k < HID; ++k)
                acc = fmaf(s_fc1w[jj * HID + k], s_h2w[k], acc);
            acc = (acc >= 0.f) ? acc : 0.2f * acc;       // LeakyReLU(0.2)
            float p = s_fc2w[jj] * acc;
            p += __shfl_xor_sync(0xffffffffu, p, 4);
            p += __shfl_xor_sync(0xffffffffu, p, 2);
            p += __shfl_xor_sync(0xffffffffu, p, 1);
            o_head = p + s_fc2b;                         // all lanes consistent
            if (lane == 0) orow[t - (SEQT - 1)] = o_head;
        }
    }
}

extern "C" void kernel_launch(void* const* d_in, const int* in_sizes, int n_in,
                              void* d_out, int out_size)
{
    const float* x    = (const float*)d_in[0];
    const float* Wih1 = (const float*)d_in[1];
    const float* Whh1 = (const float*)d_in[2];
    const float* bih1 = (const float*)d_in[3];
    const float* bhh1 = (const float*)d_in[4];
    const float* Wih2 = (const float*)d_in[5];
    const float* Whh2 = (const float*)d_in[6];
    const float* bih2 = (const float*)d_in[7];
    const float* bhh2 = (const float*)d_in[8];
    const float* fc1w = (const float*)d_in[9];
    const float* fc1b = (const float*)d_in[10];
    const float* fc2w = (const float*)d_in[11];
    const float* fc2b = (const float*)d_in[12];
    float* out = (float*)d_out;

    // 128 blocks x 512 threads: 1 CTA/SM, exactly 4 warps/SMSP, 1 element/warp
    lstm_net_kernel<<<BATCH / WPB, 32 * WPB>>>(x, Wih1, Whh1, bih1, bhh1,
                                               Wih2, Whh2, bih2, bhh2,
                                               fc1w, fc1b, fc2w, fc2b, out);
}

// round 11
// speedup vs baseline: 1.2069x; 1.2069x over previous
#include <cuda_runtime.h>
#include <cstdint>

#define HID   16
#define BATCH 2048
#define SEQT  2048
#define FUT   32
#define NOUT  (FUT + 1)
#define WPB   8            // 8 warps/CTA, 128 CTAs -> 1 CTA/SM, 2 warps/SMSP uniform

typedef unsigned long long ull;

// ---------- packed f32x2 helpers (sm_103a) ----------
__device__ __forceinline__ ull pack2(float lo, float hi) {
    ull r;
    asm("mov.b64 %0, {%1, %2};" : "=l"(r) : "f"(lo), "f"(hi));
    return r;
}
__device__ __forceinline__ void unpack2(ull v, float& lo, float& hi) {
    asm("mov.b64 {%0, %1}, %2;" : "=f"(lo), "=f"(hi) : "l"(v));
}
__device__ __forceinline__ ull fma2(ull a, ull b, ull c) {
    ull d;
    asm("fma.rn.f32x2 %0, %1, %2, %3;" : "=l"(d) : "l"(a), "l"(b), "l"(c));
    return d;
}
__device__ __forceinline__ float hadd2(ull v) {
    float lo, hi; unpack2(v, lo, hi); return lo + hi;
}

// ---------- fast activations ----------
__device__ __forceinline__ float tanh_ap(float x) {
    float y;
    asm("tanh.approx.f32 %0, %1;" : "=f"(y) : "f"(x));
    return y;
}
__device__ __forceinline__ float sigm(float x) {
    return fmaf(0.5f, tanh_ap(0.5f * x), 0.5f);
}

// One warp = TWO batch elements (lane = e*16 + j); lane owns all 4 gate rows of
// unit j (no intra-gate communication needed). Whh1 + Wih2 weights in registers;
// all of Whh2 in smem (slack-rich h2 loop; j/j+16 lanes share addresses).
// LOOKAHEAD PIPELINE: layer-1 gate activations for step t+1 are computed at
// step t (inputs p1* and x[t+1] are ready mid-step), carried as i1,f1,g1,o1.
// Iteration-top recurrence path shrinks to fma+tanh+mul. Autoregressive steps
// (inp = o_head) compute the lookahead at iteration end instead.
__global__ void __launch_bounds__(32 * WPB, 1)
lstm_net_kernel(const float* __restrict__ x,
                const float* __restrict__ Wih1, const float* __restrict__ Whh1,
                const float* __restrict__ bih1, const float* __restrict__ bhh1,
                const float* __restrict__ Wih2, const float* __restrict__ Whh2,
                const float* __restrict__ bih2, const float* __restrict__ bhh2,
                const float* __restrict__ fc1w, const float* __restrict__ fc1b,
                const float* __restrict__ fc2w, const float* __restrict__ fc2b,
                float* __restrict__ out)
{
    // Whh2 all rows, k-pair packed: [m][j] = {i,f} and {g,o} row pairs
    __shared__ ulonglong2 s_w2hif[8][HID];
    __shared__ ulonglong2 s_w2hgo[8][HID];
    // hidden-state broadcast buffers: [warp][elem][16 floats]
    __shared__ float4 s_h1[WPB][2][4];
    __shared__ float4 s_h2[WPB][2][4];
    // FC head
    __shared__ float s_fc1w[(HID / 2) * HID];
    __shared__ float s_fc1b[HID / 2];
    __shared__ float s_fc2w[HID / 2];
    __shared__ float s_fc2b;

    const int tid = threadIdx.x;
    if (tid < 128) {
        const int m = tid >> 4, jj = tid & 15;
        s_w2hif[m][jj] = make_ulonglong2(
            pack2(Whh2[jj * HID + 2 * m],          Whh2[jj * HID + 2 * m + 1]),
            pack2(Whh2[(jj + 16) * HID + 2 * m],   Whh2[(jj + 16) * HID + 2 * m + 1]));
        s_w2hgo[m][jj] = make_ulonglong2(
            pack2(Whh2[(jj + 32) * HID + 2 * m],   Whh2[(jj + 32) * HID + 2 * m + 1]),
            pack2(Whh2[(jj + 48) * HID + 2 * m],   Whh2[(jj + 48) * HID + 2 * m + 1]));
    }
    if (tid < (HID / 2) * HID) s_fc1w[tid] = fc1w[tid];
    if (tid < HID / 2) { s_fc1b[tid] = fc1b[tid]; s_fc2w[tid] = fc2w[tid]; }
    if (tid == 0) s_fc2b = fc2b[0];
    __syncthreads();

    const int lane = tid & 31;
    const int w    = tid >> 5;
    const int e    = lane >> 4;
    const int j    = lane & 15;
    const int b    = (blockIdx.x * WPB + w) * 2 + e;

    const int r0 = j, r1 = j + HID, r2 = j + 2 * HID, r3 = j + 3 * HID;

    // input weights + packed fused-bias constants
    const float wxi = Wih1[r0], wxf = Wih1[r1], wxg = Wih1[r2], wxo = Wih1[r3];
    const ull pb1i = pack2(bih1[r0] + bhh1[r0], 0.f);
    const ull pb1f = pack2(bih1[r1] + bhh1[r1], 0.f);
    const ull pb1g = pack2(bih1[r2] + bhh1[r2], 0.f);
    const ull pb1o = pack2(bih1[r3] + bhh1[r3], 0.f);
    const ull pb2i = pack2(bih2[r0] + bhh2[r0], 0.f);
    const ull pb2f = pack2(bih2[r1] + bhh2[r1], 0.f);
    const ull pb2g = pack2(bih2[r2] + bhh2[r2], 0.f);
    const ull pb2o = pack2(bih2[r3] + bhh2[r3], 0.f);

    // register-resident weights (k-pair packed): 8 arrays x 8 ull = 128 regs
    ull w1i_[8], w1f_[8], w1g_[8], w1o_[8];       // Whh1 (critical path)
    ull w2ii[8], w2if[8], w2ig[8], w2io[8];       // Wih2
#pragma unroll
    for (int m = 0; m < 8; ++m) {
        w1i_[m] = pack2(Whh1[r0 * HID + 2 * m], Whh1[r0 * HID + 2 * m + 1]);
        w1f_[m] = pack2(Whh1[r1 * HID + 2 * m], Whh1[r1 * HID + 2 * m + 1]);
        w1g_[m] = pack2(Whh1[r2 * HID + 2 * m], Whh1[r2 * HID + 2 * m + 1]);
        w1o_[m] = pack2(Whh1[r3 * HID + 2 * m], Whh1[r3 * HID + 2 * m + 1]);
        w2ii[m] = pack2(Wih2[r0 * HID + 2 * m], Wih2[r0 * HID + 2 * m + 1]);
        w2if[m] = pack2(Wih2[r1 * HID + 2 * m], Wih2[r1 * HID + 2 * m + 1]);
        w2ig[m] = pack2(Wih2[r2 * HID + 2 * m], Wih2[r2 * HID + 2 * m + 1]);
        w2io[m] = pack2(Wih2[r3 * HID + 2 * m], Wih2[r3 * HID + 2 * m + 1]);
    }

    // carried state
    float c1 = 0.f, c2 = 0.f, o_head = 0.f;
    ull p1i = pb1i, p1f = pb1f, p1g = pb1g, p1o = pb1o;
    ull p2i = pack2(0.f, 0.f), p2f = p2i, p2g = p2i, p2o = p2i;

    float* s_h1me = (float*)&s_h1[w][e];
    float* s_h2me = (float*)&s_h2[w][e];
    const ulonglong2* s_h1rd = (const ulonglong2*)&s_h1[w][e];
    const ulonglong2* s_h2rd = (const ulonglong2*)&s_h2[w][e];

    const float* xrow = x + (size_t)b * SEQT;
    float* orow = out + (size_t)b * NOUT;

    // ---- lookahead for t=0 (p1* = bias, inp = x[0]) ----
    float i1, f1, g1, o1;
    {
        const float inp0 = xrow[0];
        i1 = sigm(fmaf(wxi, inp0, hadd2(p1i)));
        f1 = sigm(fmaf(wxf, inp0, hadd2(p1f)));
        g1 = tanh_ap(fmaf(wxg, inp0, hadd2(p1g)));
        o1 = sigm(fmaf(wxo, inp0, hadd2(p1o)));
    }
    float xt = xrow[1 & (SEQT - 1)];

#pragma unroll 1
    for (int t = 0; t < SEQT + FUT; ++t) {
        // ======== layer 1 finalize (gates precomputed) ========
        c1 = fmaf(f1, c1, i1 * g1);
        const float h1 = o1 * tanh_ap(c1);

        // ==== broadcast h1; feeds Wih2 (now) + Whh1 (next, in place) ====
        s_h1me[j] = h1;
        __syncwarp();

        ull a2i = pb2i, a2f = pb2f, a2g = pb2g, a2o = pb2o;
        p1i = pb1i; p1f = pb1f; p1g = pb1g; p1o = pb1o;
#pragma unroll
        for (int q = 0; q < 4; ++q) {
            const ulonglong2 hq = s_h1rd[q];
            a2i = fma2(w2ii[2 * q], hq.x, a2i);
            a2f = fma2(w2if[2 * q], hq.x, a2f);
            a2g = fma2(w2ig[2 * q], hq.x, a2g);
            a2o = fma2(w2io[2 * q], hq.x, a2o);
            p1i = fma2(w1i_[2 * q], hq.x, p1i);
            p1f = fma2(w1f_[2 * q], hq.x, p1f);
            p1g = fma2(w1g_[2 * q], hq.x, p1g);
            p1o = fma2(w1o_[2 * q], hq.x, p1o);
            a2i = fma2(w2ii[2 * q + 1], hq.y, a2i);
            a2f = fma2(w2if[2 * q + 1], hq.y, a2f);
            a2g = fma2(w2ig[2 * q + 1], hq.y, a2g);
            a2o = fma2(w2io[2 * q + 1], hq.y, a2o);
            p1i = fma2(w1i_[2 * q + 1], hq.y, p1i);
            p1f = fma2(w1f_[2 * q + 1], hq.y, p1f);
            p1g = fma2(w1g_[2 * q + 1], hq.y, p1g);
            p1o = fma2(w1o_[2 * q + 1], hq.y, p1o);
        }

        // ==== LOOKAHEAD: layer-1 gates for step t+1 (teacher phase only) ====
        // p1* just finished; x[t+1] is independent of everything below.
        const bool teacher_next = (t + 1 < SEQT);
        if (teacher_next) {
            i1 = sigm(fmaf(wxi, xt, hadd2(p1i)));
            f1 = sigm(fmaf(wxf, xt, hadd2(p1f)));
            g1 = tanh_ap(fmaf(wxg, xt, hadd2(p1g)));
            o1 = sigm(fmaf(wxo, xt, hadd2(p1o)));
        }
        xt = xrow[(t + 2) & (SEQT - 1)];

        // ======== layer 2 gates ========
        const float vi = hadd2(a2i) + hadd2(p2i);
        const float vf = hadd2(a2f) + hadd2(p2f);
        const float vg = hadd2(a2g) + hadd2(p2g);
        const float vo = hadd2(a2o) + hadd2(p2o);
        const float i2 = sigm(vi), f2 = sigm(vf);
        const float g2 = tanh_ap(vg), o2 = sigm(vo);
        c2 = fmaf(f2, c2, i2 * g2);
        const float h2 = o2 * tanh_ap(c2);

        // ==== broadcast h2; pre-accumulate Whh2 @ h2 (weights from smem) ====
        s_h2me[j] = h2;
        __syncwarp();

        p2i = pack2(0.f, 0.f); p2f = p2i; p2g = p2i; p2o = p2i;
#pragma unroll
        for (int q = 0; q < 4; ++q) {
            const ulonglong2 hq = s_h2rd[q];
            const ulonglong2 wif0 = s_w2hif[2 * q][j];
            const ulonglong2 wgo0 = s_w2hgo[2 * q][j];
            const ulonglong2 wif1 = s_w2hif[2 * q + 1][j];
            const ulonglong2 wgo1 = s_w2hgo[2 * q + 1][j];
            p2i = fma2(wif0.x, hq.x, p2i);
            p2f = fma2(wif0.y, hq.x, p2f);
            p2g = fma2(wgo0.x, hq.x, p2g);
            p2o = fma2(wgo0.y, hq.x, p2o);
            p2i = fma2(wif1.x, hq.y, p2i);
            p2f = fma2(wif1.y, hq.y, p2f);
            p2g = fma2(wgo1.x, hq.y, p2g);
            p2o = fma2(wgo1.y, hq.y, p2o);
        }

        // ======== head (last teacher step + future steps only) ========
        if (t >= SEQT - 1) {
            const int jj = j & 7;
            float acc = s_fc1b[jj];
            const float* h2f = s_h2me;
#pragma unroll
            for (int k = 0; k < HID; ++k)
                acc = fmaf(s_fc1w[jj * HID + k], h2f[k], acc);
            acc = (acc >= 0.f) ? acc : 0.2f * acc;      // LeakyReLU(0.2)
            float p = (j < 8) ? s_fc2w[jj] * acc : 0.f;
            p += __shfl_xor_sync(0xffffffffu, p, 8);
            p += __shfl_xor_sync(0xffffffffu, p, 4);
            p += __shfl_xor_sync(0xffffffffu, p, 2);
            p += __shfl_xor_sync(0xffffffffu, p, 1);
            o_head = p + s_fc2b;
            if (j == 0) orow[t - (SEQT - 1)] = o_head;

            // lookahead for autoregressive step t+1 (inp = o_head)
            if (!teacher_next) {
                i1 = sigm(fmaf(wxi, o_head, hadd2(p1i)));
                f1 = sigm(fmaf(wxf, o_head, hadd2(p1f)));
                g1 = tanh_ap(fmaf(wxg, o_head, hadd2(p1g)));
                o1 = sigm(fmaf(wxo, o_head, hadd2(p1o)));
            }
        }
    }
}

extern "C" void kernel_launch(void* const* d_in, const int* in_sizes, int n_in,
                              void* d_out, int out_size)
{
    const float* x    = (const float*)d_in[0];
    const float* Wih1 = (const float*)d_in[1];
    const float* Whh1 = (const float*)d_in[2];
    const float* bih1 = (const float*)d_in[3];
    const float* bhh1 = (const float*)d_in[4];
    const float* Wih2 = (const float*)d_in[5];
    const float* Whh2 = (const float*)d_in[6];
    const float* bih2 = (const float*)d_in[7];
    const float* bhh2 = (const float*)d_in[8];
    const float* fc1w = (const float*)d_in[9];
    const float* fc1b = (const float*)d_in[10];
    const float* fc2w = (const float*)d_in[11];
    const float* fc2b = (const float*)d_in[12];
    float* out = (float*)d_out;

    // 128 blocks x 256 threads: 1 CTA/SM, exactly 2 warps/SMSP everywhere
    lstm_net_kernel<<<BATCH / 16, 32 * WPB>>>(x, Wih1, Whh1, bih1, bhh1,
                                              Wih2, Whh2, bih2, bhh2,
                                              fc1w, fc1b, fc2w, fc2b, out);
}